// round 3
// baseline (speedup 1.0000x reference)
#include <cuda_runtime.h>

// Row layout: x[b, 0, :] = rgb (1000 floats), x[b, 1, :] = depth (1000 floats).
// Collapsed math:  logit = d*r/1000 + d + r ; out = softmax_c(logit).
// One CTA per row. 256 threads; threads 0..249 each own one float4 (4 classes).

#define NUM_CLASSES 1000
#define VEC_PER_ROW (NUM_CLASSES / 4)   // 250
#define THREADS 256

__global__ __launch_bounds__(THREADS) void tmc_softmax_kernel(
    const float* __restrict__ x, float* __restrict__ out)
{
    const int row = blockIdx.x;
    const int t = threadIdx.x;

    const float4* __restrict__ rgb4 =
        reinterpret_cast<const float4*>(x + (size_t)row * (2 * NUM_CLASSES));
    const float4* __restrict__ dep4 =
        reinterpret_cast<const float4*>(x + (size_t)row * (2 * NUM_CLASSES) + NUM_CLASSES);
    float4* __restrict__ out4 =
        reinterpret_cast<float4*>(out + (size_t)row * NUM_CLASSES);

    float4 ev = make_float4(0.f, 0.f, 0.f, 0.f);
    float local = 0.f;

    if (t < VEC_PER_ROW) {
        float4 r4 = rgb4[t];
        float4 d4 = dep4[t];
        // logit = d*r*1e-3 + d + r  (values in [0, 2.001] -> exp safe, no max pass)
        ev.x = __expf(fmaf(d4.x * r4.x, 1e-3f, d4.x + r4.x));
        ev.y = __expf(fmaf(d4.y * r4.y, 1e-3f, d4.y + r4.y));
        ev.z = __expf(fmaf(d4.z * r4.z, 1e-3f, d4.z + r4.z));
        ev.w = __expf(fmaf(d4.w * r4.w, 1e-3f, d4.w + r4.w));
        local = (ev.x + ev.y) + (ev.z + ev.w);
    }

    // Block reduce sum over 8 warps
    #pragma unroll
    for (int off = 16; off > 0; off >>= 1)
        local += __shfl_xor_sync(0xFFFFFFFFu, local, off);

    __shared__ float warp_sums[THREADS / 32];
    __shared__ float total_s;
    const int warp = t >> 5;
    const int lane = t & 31;
    if (lane == 0) warp_sums[warp] = local;
    __syncthreads();

    if (warp == 0) {
        float v = (lane < THREADS / 32) ? warp_sums[lane] : 0.f;
        #pragma unroll
        for (int off = 4; off > 0; off >>= 1)
            v += __shfl_xor_sync(0xFFFFFFFFu, v, off);
        if (lane == 0) total_s = v;
    }
    __syncthreads();

    if (t < VEC_PER_ROW) {
        const float inv = 1.0f / total_s;
        float4 o;
        o.x = ev.x * inv;
        o.y = ev.y * inv;
        o.z = ev.z * inv;
        o.w = ev.w * inv;
        out4[t] = o;
    }
}

extern "C" void kernel_launch(void* const* d_in, const int* in_sizes, int n_in,
                              void* d_out, int out_size)
{
    const float* x = (const float*)d_in[0];
    float* out = (float*)d_out;
    const int batch = in_sizes[0] / (2 * NUM_CLASSES);   // 65536
    tmc_softmax_kernel<<<batch, THREADS>>>(x, out);
}

// round 4
// speedup vs baseline: 1.0053x; 1.0053x over previous
#include <cuda_runtime.h>

// Collapsed math: out[b,c] = softmax_c( d*r/1000 + d + r ),
// where r = x[b,0,c], d = x[b,1,c]. Values in [0, 2.001] -> exp is safe
// without a max pass.
//
// Warp-per-row, barrier-free version:
//   - one warp owns one full row (250 float4 = 1000 classes)
//   - 8 predicated iterations per lane, sum reduced with shfl_xor only
//   - no __syncthreads, no shared memory
//   - __ldcs/__stcs streaming hints (zero-reuse stream; evict-first)
//   - 8 rows per 256-thread CTA -> grid 8192

#define NUM_CLASSES 1000
#define VEC_PER_ROW (NUM_CLASSES / 4)      // 250 float4 per row per tensor
#define ROW_VEC_STRIDE (2 * VEC_PER_ROW)   // 500 float4 per (2,1000) row
#define THREADS 256
#define ROWS_PER_CTA (THREADS / 32)        // 8
#define ITERS 8                            // ceil(250/32)

__global__ __launch_bounds__(THREADS) void tmc_softmax_warprow(
    const float4* __restrict__ x4, float4* __restrict__ out4)
{
    const int warp = threadIdx.x >> 5;
    const int lane = threadIdx.x & 31;
    const size_t row = (size_t)blockIdx.x * ROWS_PER_CTA + warp;

    const float4* __restrict__ rgb = x4 + row * ROW_VEC_STRIDE;
    const float4* __restrict__ dep = rgb + VEC_PER_ROW;
    float4* __restrict__ out = out4 + row * VEC_PER_ROW;

    float4 ev[ITERS];
    float local = 0.f;

    #pragma unroll
    for (int i = 0; i < ITERS; i++) {
        const int idx = lane + 32 * i;
        if (idx < VEC_PER_ROW) {
            float4 r = __ldcs(&rgb[idx]);
            float4 d = __ldcs(&dep[idx]);
            float4 e;
            e.x = __expf(fmaf(d.x * r.x, 1e-3f, d.x + r.x));
            e.y = __expf(fmaf(d.y * r.y, 1e-3f, d.y + r.y));
            e.z = __expf(fmaf(d.z * r.z, 1e-3f, d.z + r.z));
            e.w = __expf(fmaf(d.w * r.w, 1e-3f, d.w + r.w));
            ev[i] = e;
            local += (e.x + e.y) + (e.z + e.w);
        }
    }

    // Warp-only reduction: no barriers, no smem.
    #pragma unroll
    for (int off = 16; off > 0; off >>= 1)
        local += __shfl_xor_sync(0xFFFFFFFFu, local, off);

    const float inv = 1.0f / local;

    #pragma unroll
    for (int i = 0; i < ITERS; i++) {
        const int idx = lane + 32 * i;
        if (idx < VEC_PER_ROW) {
            float4 o;
            o.x = ev[i].x * inv;
            o.y = ev[i].y * inv;
            o.z = ev[i].z * inv;
            o.w = ev[i].w * inv;
            __stcs(&out[idx], o);
        }
    }
}

extern "C" void kernel_launch(void* const* d_in, const int* in_sizes, int n_in,
                              void* d_out, int out_size)
{
    const float4* x4 = (const float4*)d_in[0];
    float4* out4 = (float4*)d_out;
    const int batch = in_sizes[0] / (2 * NUM_CLASSES);   // 65536
    tmc_softmax_warprow<<<batch / ROWS_PER_CTA, THREADS>>>(x4, out4);
}